// round 7
// baseline (speedup 1.0000x reference)
#include <cuda_runtime.h>
#include <math.h>
#include <stdint.h>

#define BSZ    2
#define LSEQ   2048
#define DMODEL 512
#define DINNER 1024
#define DSTATE 16
#define DTRANK 32
#define DCONV  4
#define NROWS  (BSZ*LSEQ)          // 4096
#define DBLC   (DTRANK + 2*DSTATE) // 64

// ---------------- scratch (device globals; no allocs allowed) ----------------
__device__ float g_xz [NROWS * 2 * DINNER];
__device__ float g_xc [NROWS * DINNER];
__device__ float g_dbl[NROWS * DBLC];
__device__ float g_dt [NROWS * DINNER];
__device__ float g_y  [NROWS * DINNER];

__device__ __forceinline__ float f2tf32(float x) {
    uint32_t u;
    asm("cvt.rna.tf32.f32 %0, %1;" : "=r"(u) : "f"(x));
    return __uint_as_float(u);
}

__device__ __forceinline__ void mma_tf32(float c[4], const uint32_t a[4],
                                         const uint32_t b[2]) {
    asm volatile(
        "mma.sync.aligned.m16n8k8.row.col.f32.tf32.tf32.f32 "
        "{%0,%1,%2,%3}, {%4,%5,%6,%7}, {%8,%9}, {%0,%1,%2,%3};"
        : "+f"(c[0]), "+f"(c[1]), "+f"(c[2]), "+f"(c[3])
        : "r"(a[0]), "r"(a[1]), "r"(a[2]), "r"(a[3]), "r"(b[0]), "r"(b[1]));
}

// ---------------------------------------------------------------------------
// TF32 warp-MMA GEMM with FRAGMENT-LAYOUT SMEM.
// C[M,N] = A[M,K](lda, row-major) @ W[K,N](ldb, row-major).
// Operands are scattered into mma fragment order at SMEM-store time, so each
// fragment load is one LDS128 (A) / LDS64 (B). XOR lane swizzles (kk for A,
// nt for B) keep scatter stores <=2-way bank conflicted.
// MODE 0: C=D.  MODE 1: C=D+RES.  MODE 2: C=softplus(D+bias).
// ---------------------------------------------------------------------------
template<int BM, int BN, int WARPS_M, int WARPS_N, int MODE>
__global__ void __launch_bounds__(WARPS_M*WARPS_N*32)
mma_gemm(const float* __restrict__ A, int lda,
         const float* __restrict__ W, int ldb,
         const float* __restrict__ RES,
         const float* __restrict__ bias,
         float* __restrict__ C, int N, int K)
{
    constexpr int BK = 32;
    constexpr int THREADS = WARPS_M*WARPS_N*32;
    constexpr int WM = BM/WARPS_M, WN = BN/WARPS_N;
    constexpr int MT = WM/16, NT = WN/8;
    constexpr int MTT = BM/16, NTT = BN/8;
    constexpr int A_ITERS = (BM*BK/4) / THREADS;
    constexpr int B_ITERS = (BN*BK/4) / THREADS;
    constexpr int BROW4 = BN/4;
    constexpr int AF_FLOATS = 4*MTT*32*4;   // [kk][mt][lane][4]
    // BF: [kk][nt][lane][2]

    extern __shared__ float sm[];
    float* AF = sm;
    float* BF = sm + AF_FLOATS;

    const int tid  = threadIdx.x;
    const int wid  = tid >> 5;
    const int lane = tid & 31;
    const int wm0  = (wid % WARPS_M) * WM;
    const int wn0  = (wid / WARPS_M) * WN;
    const int bm   = blockIdx.y * BM;
    const int bn   = blockIdx.x * BN;

    float acc[MT][NT][4];
    #pragma unroll
    for (int i = 0; i < MT; i++)
        #pragma unroll
        for (int j = 0; j < NT; j++)
            #pragma unroll
            for (int v = 0; v < 4; v++) acc[i][j][v] = 0.f;

    for (int k0 = 0; k0 < K; k0 += BK) {
        // ---- A tile -> fragment layout ----
        #pragma unroll
        for (int i = 0; i < A_ITERS; i++) {
            int idx = tid + i*THREADS;
            int r = idx >> 3, c4 = idx & 7;
            float4 v = *(const float4*)(A + (long)(bm + r)*lda + k0 + c4*4);
            int kk = c4 >> 1, kh = c4 & 1;
            int mt = r >> 4, g = r & 7, mh = (r >> 3) & 1;
            int slot = mh + 2*kh;
            float* base = AF + (size_t)((kk*MTT + mt)*32)*4 + slot;
            int L0 = g*4;
            base[(size_t)((L0+0) ^ kk)*4] = f2tf32(v.x);
            base[(size_t)((L0+1) ^ kk)*4] = f2tf32(v.y);
            base[(size_t)((L0+2) ^ kk)*4] = f2tf32(v.z);
            base[(size_t)((L0+3) ^ kk)*4] = f2tf32(v.w);
        }
        // ---- B tile (direct from row-major W[k][n]) -> fragment layout ----
        #pragma unroll
        for (int i = 0; i < B_ITERS; i++) {
            int idx = tid + i*THREADS;
            int kr = idx / BROW4, nc4 = idx % BROW4;
            float4 v = *(const float4*)(W + (long)(k0 + kr)*ldb + bn + nc4*4);
            int kk = kr >> 3, q = kr & 3, kh = (kr >> 2) & 1;
            int n0 = nc4*4;
            float vv[4] = {v.x, v.y, v.z, v.w};
            #pragma unroll
            for (int j = 0; j < 4; j++) {
                int n = n0 + j;
                int nt = n >> 3, g = n & 7;
                int lp = (g*4 + q) ^ nt;
                BF[(size_t)((kk*NTT + nt)*32 + lp)*2 + kh] = f2tf32(vv[j]);
            }
        }
        __syncthreads();

        #pragma unroll
        for (int kk = 0; kk < 4; kk++) {
            uint32_t ah[MT][4], bh[NT][2];
            #pragma unroll
            for (int i = 0; i < MT; i++) {
                int mt = (wm0 >> 4) + i;
                float4 av = *(const float4*)(AF + (size_t)((kk*MTT + mt)*32 + (lane ^ kk))*4);
                ah[i][0] = __float_as_uint(av.x);
                ah[i][1] = __float_as_uint(av.y);
                ah[i][2] = __float_as_uint(av.z);
                ah[i][3] = __float_as_uint(av.w);
            }
            #pragma unroll
            for (int j = 0; j < NT; j++) {
                int nt = (wn0 >> 3) + j;
                float2 bv = *(const float2*)(BF + (size_t)((kk*NTT + nt)*32 + (lane ^ nt))*2);
                bh[j][0] = __float_as_uint(bv.x);
                bh[j][1] = __float_as_uint(bv.y);
            }
            #pragma unroll
            for (int i = 0; i < MT; i++)
                #pragma unroll
                for (int j = 0; j < NT; j++)
                    mma_tf32(acc[i][j], ah[i], bh[j]);
        }
        __syncthreads();
    }

    // epilogue (same mapping as verified R5 kernel)
    const int g = lane >> 2, q = lane & 3;
    #pragma unroll
    for (int i = 0; i < MT; i++) {
        #pragma unroll
        for (int half = 0; half < 2; half++) {
            int row = bm + wm0 + i*16 + g + half*8;
            #pragma unroll
            for (int j = 0; j < NT; j++) {
                int col = bn + wn0 + j*8 + 2*q;
                float v0 = acc[i][j][half*2 + 0];
                float v1 = acc[i][j][half*2 + 1];
                long base = (long)row*N + col;
                if (MODE == 1) {
                    v0 += RES[base]; v1 += RES[base + 1];
                } else if (MODE == 2) {
                    v0 += bias[col]; v1 += bias[col + 1];
                    v0 = (v0 > 20.f) ? v0 : log1pf(expf(v0));
                    v1 = (v1 > 20.f) ? v1 : log1pf(expf(v1));
                }
                *(float2*)(C + base) = make_float2(v0, v1);
            }
        }
    }
}

// ---------------------------------------------------------------------------
// Depthwise causal conv (4 taps) + bias + silu
// ---------------------------------------------------------------------------
__global__ void conv_silu_kernel(const float* __restrict__ conv_w,
                                 const float* __restrict__ conv_b)
{
    int idx = blockIdx.x * blockDim.x + threadIdx.x;
    int row = idx >> 10;
    int d   = idx & 1023;
    int l   = row & (LSEQ - 1);

    float acc = conv_b[d];
    #pragma unroll
    for (int j = 0; j < DCONV; j++) {
        int ls = l - (DCONV - 1) + j;
        if (ls >= 0)
            acc += conv_w[d*DCONV + j] * g_xz[(long)(row - (DCONV-1) + j)*(2*DINNER) + d];
    }
    float sig = 1.f / (1.f + __expf(-acc));
    g_xc[idx] = acc * sig;
}

// ---------------------------------------------------------------------------
// Selective scan with software prefetch. 256 blocks x 128 threads.
// ---------------------------------------------------------------------------
__device__ __forceinline__ void scan_loadblk(int row, int d, int s,
                                             float dtv[8], float xv[8],
                                             float Bv[8], float Cv[8])
{
    #pragma unroll
    for (int u = 0; u < 8; u++) {
        int r = row + u;
        dtv[u] = g_dt [(long)r*DINNER + d];
        xv [u] = g_xc [(long)r*DINNER + d];
        Bv [u] = g_dbl[(long)r*DBLC + DTRANK + s];
        Cv [u] = g_dbl[(long)r*DBLC + DTRANK + DSTATE + s];
    }
}

__global__ void __launch_bounds__(128) scan_kernel(const float* __restrict__ A_log,
                                                   const float* __restrict__ Dvec)
{
    int gid = blockIdx.x * 128 + threadIdx.x;
    int s = gid & 15;
    int c = gid >> 4;
    int b = c >> 10;
    int d = c & 1023;

    const float A  = -expf(A_log[d*DSTATE + s]);
    const float Dv = Dvec[d];
    float h = 0.f;

    int row = b * LSEQ;
    float dtv[8], xv[8], Bv[8], Cv[8];
    scan_loadblk(row, d, s, dtv, xv, Bv, Cv);

    for (int l = 0; l < LSEQ; l += 8, row += 8) {
        float ndt[8], nxv[8], nBv[8], nCv[8];
        if (l + 8 < LSEQ)
            scan_loadblk(row + 8, d, s, ndt, nxv, nBv, nCv);

        float p[8];
        #pragma unroll
        for (int u = 0; u < 8; u++) {
            float dA = __expf(dtv[u] * A);
            h = h * dA + (dtv[u] * xv[u]) * Bv[u];
            p[u] = h * Cv[u];
        }
        #pragma unroll
        for (int off = 8; off; off >>= 1) {
            #pragma unroll
            for (int u = 0; u < 8; u++)
                p[u] += __shfl_xor_sync(0xffffffffu, p[u], off);
        }
        if (s == 0) {
            #pragma unroll
            for (int u = 0; u < 8; u++) {
                int r = row + u;
                float zv  = g_xz[(long)r*(2*DINNER) + DINNER + d];
                float sig = 1.f / (1.f + __expf(-zv));
                g_y[(long)r*DINNER + d] = (p[u] + xv[u]*Dv) * (zv * sig);
            }
        }
        #pragma unroll
        for (int u = 0; u < 8; u++) {
            dtv[u] = ndt[u]; xv[u] = nxv[u]; Bv[u] = nBv[u]; Cv[u] = nCv[u];
        }
    }
}

// ---------------------------------------------------------------------------
// LayerNorm over rows of 512 (in-place)
// ---------------------------------------------------------------------------
__global__ void ln_kernel(float* __restrict__ out,
                          const float* __restrict__ gamma,
                          const float* __restrict__ beta)
{
    int row = blockIdx.x;
    int t   = threadIdx.x;
    float v0 = out[(long)row*DMODEL + t];
    float v1 = out[(long)row*DMODEL + 256 + t];

    float s = v0 + v1;
    float qq = v0*v0 + v1*v1;
    #pragma unroll
    for (int o = 16; o; o >>= 1) {
        s  += __shfl_xor_sync(0xffffffffu, s, o);
        qq += __shfl_xor_sync(0xffffffffu, qq, o);
    }
    __shared__ float s1[8], s2[8];
    int wid = t >> 5, lane = t & 31;
    if (lane == 0) { s1[wid] = s; s2[wid] = qq; }
    __syncthreads();
    if (t == 0) {
        float ts = 0.f, tq = 0.f;
        #pragma unroll
        for (int i = 0; i < 8; i++) { ts += s1[i]; tq += s2[i]; }
        float mu = ts / DMODEL;
        s1[0] = mu;
        s2[0] = tq / DMODEL - mu*mu;
    }
    __syncthreads();
    float mu  = s1[0];
    float inv = rsqrtf(s2[0] + 1e-5f);
    out[(long)row*DMODEL + t]       = (v0 - mu) * inv * gamma[t]       + beta[t];
    out[(long)row*DMODEL + 256 + t] = (v1 - mu) * inv * gamma[256 + t] + beta[256 + t];
}

// ---------------------------------------------------------------------------
extern "C" void kernel_launch(void* const* d_in, const int* in_sizes, int n_in,
                              void* d_out, int out_size)
{
    const float* x      = (const float*)d_in[0];
    const float* W_in   = (const float*)d_in[1];
    const float* conv_w = (const float*)d_in[2];
    const float* conv_b = (const float*)d_in[3];
    const float* W_xprj = (const float*)d_in[4];
    const float* W_dt   = (const float*)d_in[5];
    const float* b_dt   = (const float*)d_in[6];
    const float* A_log  = (const float*)d_in[7];
    const float* Dvec   = (const float*)d_in[8];
    const float* W_out  = (const float*)d_in[9];
    const float* gamma  = (const float*)d_in[10];
    const float* beta   = (const float*)d_in[11];
    float* out = (float*)d_out;

    float *xz, *xc, *dbl, *dt, *y;
    cudaGetSymbolAddress((void**)&xz,  g_xz);
    cudaGetSymbolAddress((void**)&xc,  g_xc);
    cudaGetSymbolAddress((void**)&dbl, g_dbl);
    cudaGetSymbolAddress((void**)&dt,  g_dt);
    cudaGetSymbolAddress((void**)&y,   g_y);

    // SMEM: AF = 32*BM floats, BF = 32*BN floats
    const int SM128 = (32*128 + 32*128)*4;  // 32768
    const int SM64  = (32*64  + 32*64 )*4;  // 16384

    // 0) xz = x @ W_in   (4096 x 2048, K=512)
    mma_gemm<128,128,4,2,0><<<dim3(2*DINNER/128, NROWS/128), 256, SM128>>>(
        x, DMODEL, W_in, 2*DINNER, nullptr, nullptr, xz, 2*DINNER, DMODEL);

    // 1) conv + silu
    conv_silu_kernel<<<NROWS*DINNER/256, 256>>>(conv_w, conv_b);

    // 2) dbl = xc @ W_xproj   (4096 x 64, K=1024)
    mma_gemm<64,64,2,2,0><<<dim3(1, NROWS/64), 128, SM64>>>(
        xc, DINNER, W_xprj, DBLC, nullptr, nullptr, dbl, DBLC, DINNER);

    // 3) dt = softplus(dtr @ W_dt + b_dt)   (4096 x 1024, K=32)
    mma_gemm<128,128,4,2,2><<<dim3(DINNER/128, NROWS/128), 256, SM128>>>(
        dbl, DBLC, W_dt, DINNER, nullptr, b_dt, dt, DINNER, DTRANK);

    // 4) selective scan
    scan_kernel<<<(BSZ*DINNER*DSTATE)/128, 128>>>(A_log, Dvec);

    // 5) h2 = y @ W_out + x
    mma_gemm<128,128,4,2,1><<<dim3(DMODEL/128, NROWS/128), 256, SM128>>>(
        y, DINNER, W_out, DMODEL, x, nullptr, out, DMODEL, DINNER);

    // 6) LayerNorm
    ln_kernel<<<NROWS, 256>>>(out, gamma, beta);
}

// round 9
// speedup vs baseline: 1.3591x; 1.3591x over previous
#include <cuda_runtime.h>
#include <math.h>
#include <stdint.h>

#define BSZ    2
#define LSEQ   2048
#define DMODEL 512
#define DINNER 1024
#define DSTATE 16
#define DTRANK 32
#define DCONV  4
#define NROWS  (BSZ*LSEQ)          // 4096
#define DBLC   (DTRANK + 2*DSTATE) // 64

// ---------------- scratch (device globals; no allocs allowed) ----------------
__device__ float g_xz [NROWS * 2 * DINNER];
__device__ float g_xc [NROWS * DINNER];
__device__ float g_dbl[NROWS * DBLC];
__device__ float g_dt [NROWS * DINNER];
__device__ float g_y  [NROWS * DINNER];

__device__ __forceinline__ float f2tf32(float x) {
    uint32_t u;
    asm("cvt.rna.tf32.f32 %0, %1;" : "=r"(u) : "f"(x));
    return __uint_as_float(u);
}

__device__ __forceinline__ void mma_tf32(float c[4], const uint32_t a[4],
                                         const uint32_t b[2]) {
    asm volatile(
        "mma.sync.aligned.m16n8k8.row.col.f32.tf32.tf32.f32 "
        "{%0,%1,%2,%3}, {%4,%5,%6,%7}, {%8,%9}, {%0,%1,%2,%3};"
        : "+f"(c[0]), "+f"(c[1]), "+f"(c[2]), "+f"(c[3])
        : "r"(a[0]), "r"(a[1]), "r"(a[2]), "r"(a[3]), "r"(b[0]), "r"(b[1]));
}

// Conflict-free XOR swizzle for [k][m]-style tiles (verified bank math):
//   loads:  bank = (m ^ 8q ^ C) -> 32 distinct over (q, g)
//   stores: bank = (r ^ 8cc ^ 4c4) -> 32 distinct over (r, c4)
template<int LD>
__device__ __forceinline__ int swz(int c, int m) {
    return c*LD + (m ^ ((c & 3) << 3) ^ (((c >> 2) & 7) << 2));
}

// ---------------------------------------------------------------------------
// Single-pass TF32 warp-MMA GEMM, swizzled SMEM, direct row-major W[K,N].
// C[M,N] = A[M,K](lda) @ W[K,N](ldb).
// MODE 0: C=D.  MODE 1: C=D+RES.  MODE 2: C=softplus(D+bias).
// ---------------------------------------------------------------------------
template<int BM, int BN, int WARPS_M, int WARPS_N, int MODE>
__global__ void __launch_bounds__(WARPS_M*WARPS_N*32)
mma_gemm(const float* __restrict__ A, int lda,
         const float* __restrict__ W, int ldb,
         const float* __restrict__ RES,
         const float* __restrict__ bias,
         float* __restrict__ C, int N, int K)
{
    constexpr int BK = 32;
    constexpr int THREADS = WARPS_M*WARPS_N*32;
    constexpr int WM = BM/WARPS_M, WN = BN/WARPS_N;
    constexpr int MT = WM/16, NT = WN/8;
    constexpr int A_ITERS = (BM*BK/4) / THREADS;
    constexpr int B_ITERS = (BN*BK/4) / THREADS;
    constexpr int BROW4 = BN/4;

    extern __shared__ float sm[];
    float* As = sm;             // BK*BM floats, swizzled [k][m]
    float* Bs = sm + BK*BM;     // BK*BN floats, swizzled [k][n]

    const int tid  = threadIdx.x;
    const int wid  = tid >> 5;
    const int lane = tid & 31;
    const int g    = lane >> 2;
    const int q    = lane & 3;
    const int wm0  = (wid % WARPS_M) * WM;
    const int wn0  = (wid / WARPS_M) * WN;
    const int bm   = blockIdx.y * BM;
    const int bn   = blockIdx.x * BN;

    float acc[MT][NT][4];
    #pragma unroll
    for (int i = 0; i < MT; i++)
        #pragma unroll
        for (int j = 0; j < NT; j++)
            #pragma unroll
            for (int v = 0; v < 4; v++) acc[i][j][v] = 0.f;

    for (int k0 = 0; k0 < K; k0 += BK) {
        // A tile -> swizzled [k][m]
        #pragma unroll
        for (int i = 0; i < A_ITERS; i++) {
            int idx = tid + i*THREADS;
            int r = idx >> 3, c4 = idx & 7;
            float4 v = *(const float4*)(A + (long)(bm + r)*lda + k0 + c4*4);
            As[swz<BM>(c4*4+0, r)] = f2tf32(v.x);
            As[swz<BM>(c4*4+1, r)] = f2tf32(v.y);
            As[swz<BM>(c4*4+2, r)] = f2tf32(v.z);
            As[swz<BM>(c4*4+3, r)] = f2tf32(v.w);
        }
        // B tile (row-major W) -> swizzled [k][n], vector stores
        #pragma unroll
        for (int i = 0; i < B_ITERS; i++) {
            int idx = tid + i*THREADS;
            int kr = idx / BROW4, nc4 = idx % BROW4;
            float4 v = *(const float4*)(W + (long)(k0 + kr)*ldb + bn + nc4*4);
            float4 t;
            t.x = f2tf32(v.x); t.y = f2tf32(v.y);
            t.z = f2tf32(v.z); t.w = f2tf32(v.w);
            *(float4*)(Bs + swz<BN>(kr, nc4*4)) = t;
        }
        __syncthreads();

        #pragma unroll
        for (int kk = 0; kk < 4; kk++) {
            const int kb = kk*8;
            uint32_t ah[MT][4], bh[NT][2];
            #pragma unroll
            for (int i = 0; i < MT; i++) {
                int m0 = wm0 + i*16 + g;
                ah[i][0] = __float_as_uint(As[swz<BM>(kb+q,   m0    )]);
                ah[i][1] = __float_as_uint(As[swz<BM>(kb+q,   m0 + 8)]);
                ah[i][2] = __float_as_uint(As[swz<BM>(kb+q+4, m0    )]);
                ah[i][3] = __float_as_uint(As[swz<BM>(kb+q+4, m0 + 8)]);
            }
            #pragma unroll
            for (int j = 0; j < NT; j++) {
                int n0 = wn0 + j*8 + g;
                bh[j][0] = __float_as_uint(Bs[swz<BN>(kb+q,   n0)]);
                bh[j][1] = __float_as_uint(Bs[swz<BN>(kb+q+4, n0)]);
            }
            #pragma unroll
            for (int i = 0; i < MT; i++)
                #pragma unroll
                for (int j = 0; j < NT; j++)
                    mma_tf32(acc[i][j], ah[i], bh[j]);
        }
        __syncthreads();
    }

    // epilogue (same mapping as verified R5 kernel)
    #pragma unroll
    for (int i = 0; i < MT; i++) {
        #pragma unroll
        for (int half = 0; half < 2; half++) {
            int row = bm + wm0 + i*16 + g + half*8;
            #pragma unroll
            for (int j = 0; j < NT; j++) {
                int col = bn + wn0 + j*8 + 2*q;
                float v0 = acc[i][j][half*2 + 0];
                float v1 = acc[i][j][half*2 + 1];
                long base = (long)row*N + col;
                if (MODE == 1) {
                    v0 += RES[base]; v1 += RES[base + 1];
                } else if (MODE == 2) {
                    v0 += bias[col]; v1 += bias[col + 1];
                    v0 = (v0 > 20.f) ? v0 : log1pf(expf(v0));
                    v1 = (v1 > 20.f) ? v1 : log1pf(expf(v1));
                }
                *(float2*)(C + base) = make_float2(v0, v1);
            }
        }
    }
}

// ---------------------------------------------------------------------------
// Fused conv+silu+xproj: per CTA row-block, the A-tile loader computes
// xc = silu(causal_conv(xz[:, :1024])) on the fly, writes fp32 xc to gmem
// (for the scan) and tf32 to swizzled SMEM (for the MMA). Then dbl = xc@W_xproj.
// BM=64, BN=64, K=1024, 128 threads (2x2 warps, WM=WN=32).
// ---------------------------------------------------------------------------
__global__ void __launch_bounds__(128)
xproj_conv_kernel(const float* __restrict__ conv_w,
                  const float* __restrict__ conv_b,
                  const float* __restrict__ Wx)   // [1024 x 64]
{
    constexpr int BM = 64, BN = 64, BK = 32;
    constexpr int MT = 2, NT = 4;   // WM=32, WN=32

    __shared__ float As[BK*BM];
    __shared__ float Bs[BK*BN];

    const int tid  = threadIdx.x;
    const int wid  = tid >> 5;
    const int lane = tid & 31;
    const int g    = lane >> 2;
    const int q    = lane & 3;
    const int wm0  = (wid & 1) * 32;
    const int wn0  = (wid >> 1) * 32;
    const int bm   = blockIdx.x * BM;

    float acc[MT][NT][4];
    #pragma unroll
    for (int i = 0; i < MT; i++)
        #pragma unroll
        for (int j = 0; j < NT; j++)
            #pragma unroll
            for (int v = 0; v < 4; v++) acc[i][j][v] = 0.f;

    for (int k0 = 0; k0 < DINNER; k0 += BK) {
        // A tile: conv+silu computed inline (4 float4 loads per element-group)
        #pragma unroll
        for (int i = 0; i < 4; i++) {            // BM*BK/4/128 = 4
            int idx = tid + i*128;
            int r = idx >> 3, c4 = idx & 7;
            int m = bm + r;
            int l = m & (LSEQ - 1);
            int k = k0 + c4*4;

            float tv[4][4];
            #pragma unroll
            for (int j = 0; j < 4; j++) {
                float4 t = make_float4(0.f, 0.f, 0.f, 0.f);
                if (l - 3 + j >= 0)
                    t = *(const float4*)(g_xz + (long)(m - 3 + j)*(2*DINNER) + k);
                tv[j][0] = t.x; tv[j][1] = t.y; tv[j][2] = t.z; tv[j][3] = t.w;
            }
            float4 cb = *(const float4*)(conv_b + k);
            float cbv[4] = {cb.x, cb.y, cb.z, cb.w};
            float xo[4];
            #pragma unroll
            for (int cc = 0; cc < 4; cc++) {
                float4 w = *(const float4*)(conv_w + (k + cc)*DCONV);
                float a = cbv[cc] + w.x*tv[0][cc] + w.y*tv[1][cc]
                                  + w.z*tv[2][cc] + w.w*tv[3][cc];
                float sig = 1.f / (1.f + __expf(-a));
                xo[cc] = a * sig;
                As[swz<BM>(c4*4 + cc, r)] = f2tf32(xo[cc]);
            }
            *(float4*)(g_xc + (long)m*DINNER + k) =
                make_float4(xo[0], xo[1], xo[2], xo[3]);
        }
        // B tile: W_xproj rows k0..k0+31, all 64 cols
        #pragma unroll
        for (int i = 0; i < 4; i++) {            // BN*BK/4/128 = 4
            int idx = tid + i*128;
            int kr = idx >> 4, nc4 = idx & 15;
            float4 v = *(const float4*)(Wx + (long)(k0 + kr)*DBLC + nc4*4);
            float4 t;
            t.x = f2tf32(v.x); t.y = f2tf32(v.y);
            t.z = f2tf32(v.z); t.w = f2tf32(v.w);
            *(float4*)(Bs + swz<BN>(kr, nc4*4)) = t;
        }
        __syncthreads();

        #pragma unroll
        for (int kk = 0; kk < 4; kk++) {
            const int kb = kk*8;
            uint32_t ah[MT][4], bh[NT][2];
            #pragma unroll
            for (int i = 0; i < MT; i++) {
                int m0 = wm0 + i*16 + g;
                ah[i][0] = __float_as_uint(As[swz<BM>(kb+q,   m0    )]);
                ah[i][1] = __float_as_uint(As[swz<BM>(kb+q,   m0 + 8)]);
                ah[i][2] = __float_as_uint(As[swz<BM>(kb+q+4, m0    )]);
                ah[i][3] = __float_as_uint(As[swz<BM>(kb+q+4, m0 + 8)]);
            }
            #pragma unroll
            for (int j = 0; j < NT; j++) {
                int n0 = wn0 + j*8 + g;
                bh[j][0] = __float_as_uint(Bs[swz<BN>(kb+q,   n0)]);
                bh[j][1] = __float_as_uint(Bs[swz<BN>(kb+q+4, n0)]);
            }
            #pragma unroll
            for (int i = 0; i < MT; i++)
                #pragma unroll
                for (int j = 0; j < NT; j++)
                    mma_tf32(acc[i][j], ah[i], bh[j]);
        }
        __syncthreads();
    }

    #pragma unroll
    for (int i = 0; i < MT; i++) {
        #pragma unroll
        for (int half = 0; half < 2; half++) {
            int row = bm + wm0 + i*16 + g + half*8;
            #pragma unroll
            for (int j = 0; j < NT; j++) {
                int col = wn0 + j*8 + 2*q;
                *(float2*)(g_dbl + (long)row*DBLC + col) =
                    make_float2(acc[i][j][half*2 + 0], acc[i][j][half*2 + 1]);
            }
        }
    }
}

// ---------------------------------------------------------------------------
// Selective scan with software prefetch. 128 threads/block.
// ---------------------------------------------------------------------------
__device__ __forceinline__ void scan_loadblk(int row, int d, int s,
                                             float dtv[8], float xv[8],
                                             float Bv[8], float Cv[8])
{
    #pragma unroll
    for (int u = 0; u < 8; u++) {
        int r = row + u;
        dtv[u] = g_dt [(long)r*DINNER + d];
        xv [u] = g_xc [(long)r*DINNER + d];
        Bv [u] = g_dbl[(long)r*DBLC + DTRANK + s];
        Cv [u] = g_dbl[(long)r*DBLC + DTRANK + DSTATE + s];
    }
}

__global__ void __launch_bounds__(128) scan_kernel(const float* __restrict__ A_log,
                                                   const float* __restrict__ Dvec)
{
    int gid = blockIdx.x * 128 + threadIdx.x;
    int s = gid & 15;
    int c = gid >> 4;
    int b = c >> 10;
    int d = c & 1023;

    const float A  = -expf(A_log[d*DSTATE + s]);
    const float Dv = Dvec[d];
    float h = 0.f;

    int row = b * LSEQ;
    float dtv[8], xv[8], Bv[8], Cv[8];
    scan_loadblk(row, d, s, dtv, xv, Bv, Cv);

    for (int l = 0; l < LSEQ; l += 8, row += 8) {
        float ndt[8], nxv[8], nBv[8], nCv[8];
        if (l + 8 < LSEQ)
            scan_loadblk(row + 8, d, s, ndt, nxv, nBv, nCv);

        float p[8];
        #pragma unroll
        for (int u = 0; u < 8; u++) {
            float dA = __expf(dtv[u] * A);
            h = h * dA + (dtv[u] * xv[u]) * Bv[u];
            p[u] = h * Cv[u];
        }
        #pragma unroll
        for (int off = 8; off; off >>= 1) {
            #pragma unroll
            for (int u = 0; u < 8; u++)
                p[u] += __shfl_xor_sync(0xffffffffu, p[u], off);
        }
        if (s == 0) {
            #pragma unroll
            for (int u = 0; u < 8; u++) {
                int r = row + u;
                float zv  = g_xz[(long)r*(2*DINNER) + DINNER + d];
                float sig = 1.f / (1.f + __expf(-zv));
                g_y[(long)r*DINNER + d] = (p[u] + xv[u]*Dv) * (zv * sig);
            }
        }
        #pragma unroll
        for (int u = 0; u < 8; u++) {
            dtv[u] = ndt[u]; xv[u] = nxv[u]; Bv[u] = nBv[u]; Cv[u] = nCv[u];
        }
    }
}

// ---------------------------------------------------------------------------
// LayerNorm over rows of 512 (in-place)
// ---------------------------------------------------------------------------
__global__ void ln_kernel(float* __restrict__ out,
                          const float* __restrict__ gamma,
                          const float* __restrict__ beta)
{
    int row = blockIdx.x;
    int t   = threadIdx.x;
    float v0 = out[(long)row*DMODEL + t];
    float v1 = out[(long)row*DMODEL + 256 + t];

    float s = v0 + v1;
    float qq = v0*v0 + v1*v1;
    #pragma unroll
    for (int o = 16; o; o >>= 1) {
        s  += __shfl_xor_sync(0xffffffffu, s, o);
        qq += __shfl_xor_sync(0xffffffffu, qq, o);
    }
    __shared__ float s1[8], s2[8];
    int wid = t >> 5, lane = t & 31;
    if (lane == 0) { s1[wid] = s; s2[wid] = qq; }
    __syncthreads();
    if (t == 0) {
        float ts = 0.f, tq = 0.f;
        #pragma unroll
        for (int i = 0; i < 8; i++) { ts += s1[i]; tq += s2[i]; }
        float mu = ts / DMODEL;
        s1[0] = mu;
        s2[0] = tq / DMODEL - mu*mu;
    }
    __syncthreads();
    float mu  = s1[0];
    float inv = rsqrtf(s2[0] + 1e-5f);
    out[(long)row*DMODEL + t]       = (v0 - mu) * inv * gamma[t]       + beta[t];
    out[(long)row*DMODEL + 256 + t] = (v1 - mu) * inv * gamma[256 + t] + beta[256 + t];
}

// ---------------------------------------------------------------------------
extern "C" void kernel_launch(void* const* d_in, const int* in_sizes, int n_in,
                              void* d_out, int out_size)
{
    const float* x      = (const float*)d_in[0];
    const float* W_in   = (const float*)d_in[1];
    const float* conv_w = (const float*)d_in[2];
    const float* conv_b = (const float*)d_in[3];
    const float* W_xprj = (const float*)d_in[4];
    const float* W_dt   = (const float*)d_in[5];
    const float* b_dt   = (const float*)d_in[6];
    const float* A_log  = (const float*)d_in[7];
    const float* Dvec   = (const float*)d_in[8];
    const float* W_out  = (const float*)d_in[9];
    const float* gamma  = (const float*)d_in[10];
    const float* beta   = (const float*)d_in[11];
    float* out = (float*)d_out;

    float *xz, *dbl, *dt, *y;
    cudaGetSymbolAddress((void**)&xz,  g_xz);
    cudaGetSymbolAddress((void**)&dbl, g_dbl);
    cudaGetSymbolAddress((void**)&dt,  g_dt);
    cudaGetSymbolAddress((void**)&y,   g_y);

    const int SM128 = (32*128 + 32*128)*4;  // 32768

    // 0) xz = x @ W_in   (4096 x 2048, K=512)
    mma_gemm<128,128,4,2,0><<<dim3(2*DINNER/128, NROWS/128), 256, SM128>>>(
        x, DMODEL, W_in, 2*DINNER, nullptr, nullptr, xz, 2*DINNER, DMODEL);

    // 1) fused conv+silu+xproj: xc (gmem) + dbl = xc @ W_xproj
    xproj_conv_kernel<<<NROWS/64, 128>>>(conv_w, conv_b, W_xprj);

    // 2) dt = softplus(dtr @ W_dt + b_dt)   (4096 x 1024, K=32)
    mma_gemm<128,128,4,2,2><<<dim3(DINNER/128, NROWS/128), 256, SM128>>>(
        dbl, DBLC, W_dt, DINNER, nullptr, b_dt, dt, DINNER, DTRANK);

    // 3) selective scan  (launch index 3 -> ncu capture target)
    scan_kernel<<<(BSZ*DINNER*DSTATE)/128, 128>>>(A_log, Dvec);

    // 4) h2 = y @ W_out + x
    mma_gemm<128,128,4,2,1><<<dim3(DMODEL/128, NROWS/128), 256, SM128>>>(
        y, DINNER, W_out, DMODEL, x, nullptr, out, DMODEL, DINNER);

    // 5) LayerNorm
    ln_kernel<<<NROWS, 256>>>(out, gamma, beta);
}

// round 10
// speedup vs baseline: 2.8696x; 2.1114x over previous
#include <cuda_runtime.h>
#include <math.h>
#include <stdint.h>

#define BSZ    2
#define LSEQ   2048
#define DMODEL 512
#define DINNER 1024
#define DSTATE 16
#define DTRANK 32
#define DCONV  4
#define NROWS  (BSZ*LSEQ)          // 4096
#define DBLC   (DTRANK + 2*DSTATE) // 64
#define NCH    8                   // scan chunks per sequence
#define CL     (LSEQ/NCH)          // 256 steps per chunk

// ---------------- scratch (device globals; no allocs allowed) ----------------
__device__ float g_xz  [NROWS * 2 * DINNER];
__device__ float g_xc  [NROWS * DINNER];
__device__ float g_dbl [NROWS * DBLC];
__device__ float g_dt  [NROWS * DINNER];
__device__ float g_y   [NROWS * DINNER];
__device__ float g_hend[BSZ*NCH*DINNER*DSTATE];  // per-chunk end state
__device__ float g_pend[BSZ*NCH*DINNER*DSTATE];  // per-chunk dA product
__device__ float g_hin [BSZ*NCH*DINNER*DSTATE];  // per-chunk incoming state

__device__ __forceinline__ float f2tf32(float x) {
    uint32_t u;
    asm("cvt.rna.tf32.f32 %0, %1;" : "=r"(u) : "f"(x));
    return __uint_as_float(u);
}

__device__ __forceinline__ void mma_tf32(float c[4], const uint32_t a[4],
                                         const uint32_t b[2]) {
    asm volatile(
        "mma.sync.aligned.m16n8k8.row.col.f32.tf32.tf32.f32 "
        "{%0,%1,%2,%3}, {%4,%5,%6,%7}, {%8,%9}, {%0,%1,%2,%3};"
        : "+f"(c[0]), "+f"(c[1]), "+f"(c[2]), "+f"(c[3])
        : "r"(a[0]), "r"(a[1]), "r"(a[2]), "r"(a[3]), "r"(b[0]), "r"(b[1]));
}

// Conflict-free XOR swizzle for [k][m] tiles (verified bank math).
template<int LD>
__device__ __forceinline__ int swz(int c, int m) {
    return c*LD + (m ^ ((c & 3) << 3) ^ (((c >> 2) & 7) << 2));
}

// ---------------------------------------------------------------------------
// Single-pass TF32 warp-MMA GEMM (unchanged from passing R8 kernel).
// ---------------------------------------------------------------------------
template<int BM, int BN, int WARPS_M, int WARPS_N, int MODE>
__global__ void __launch_bounds__(WARPS_M*WARPS_N*32)
mma_gemm(const float* __restrict__ A, int lda,
         const float* __restrict__ W, int ldb,
         const float* __restrict__ RES,
         const float* __restrict__ bias,
         float* __restrict__ C, int N, int K)
{
    constexpr int BK = 32;
    constexpr int THREADS = WARPS_M*WARPS_N*32;
    constexpr int WM = BM/WARPS_M, WN = BN/WARPS_N;
    constexpr int MT = WM/16, NT = WN/8;
    constexpr int A_ITERS = (BM*BK/4) / THREADS;
    constexpr int B_ITERS = (BN*BK/4) / THREADS;
    constexpr int BROW4 = BN/4;

    extern __shared__ float sm[];
    float* As = sm;
    float* Bs = sm + BK*BM;

    const int tid  = threadIdx.x;
    const int wid  = tid >> 5;
    const int lane = tid & 31;
    const int g    = lane >> 2;
    const int q    = lane & 3;
    const int wm0  = (wid % WARPS_M) * WM;
    const int wn0  = (wid / WARPS_M) * WN;
    const int bm   = blockIdx.y * BM;
    const int bn   = blockIdx.x * BN;

    float acc[MT][NT][4];
    #pragma unroll
    for (int i = 0; i < MT; i++)
        #pragma unroll
        for (int j = 0; j < NT; j++)
            #pragma unroll
            for (int v = 0; v < 4; v++) acc[i][j][v] = 0.f;

    for (int k0 = 0; k0 < K; k0 += BK) {
        #pragma unroll
        for (int i = 0; i < A_ITERS; i++) {
            int idx = tid + i*THREADS;
            int r = idx >> 3, c4 = idx & 7;
            float4 v = *(const float4*)(A + (long)(bm + r)*lda + k0 + c4*4);
            As[swz<BM>(c4*4+0, r)] = f2tf32(v.x);
            As[swz<BM>(c4*4+1, r)] = f2tf32(v.y);
            As[swz<BM>(c4*4+2, r)] = f2tf32(v.z);
            As[swz<BM>(c4*4+3, r)] = f2tf32(v.w);
        }
        #pragma unroll
        for (int i = 0; i < B_ITERS; i++) {
            int idx = tid + i*THREADS;
            int kr = idx / BROW4, nc4 = idx % BROW4;
            float4 v = *(const float4*)(W + (long)(k0 + kr)*ldb + bn + nc4*4);
            float4 t;
            t.x = f2tf32(v.x); t.y = f2tf32(v.y);
            t.z = f2tf32(v.z); t.w = f2tf32(v.w);
            *(float4*)(Bs + swz<BN>(kr, nc4*4)) = t;
        }
        __syncthreads();

        #pragma unroll
        for (int kk = 0; kk < 4; kk++) {
            const int kb = kk*8;
            uint32_t ah[MT][4], bh[NT][2];
            #pragma unroll
            for (int i = 0; i < MT; i++) {
                int m0 = wm0 + i*16 + g;
                ah[i][0] = __float_as_uint(As[swz<BM>(kb+q,   m0    )]);
                ah[i][1] = __float_as_uint(As[swz<BM>(kb+q,   m0 + 8)]);
                ah[i][2] = __float_as_uint(As[swz<BM>(kb+q+4, m0    )]);
                ah[i][3] = __float_as_uint(As[swz<BM>(kb+q+4, m0 + 8)]);
            }
            #pragma unroll
            for (int j = 0; j < NT; j++) {
                int n0 = wn0 + j*8 + g;
                bh[j][0] = __float_as_uint(Bs[swz<BN>(kb+q,   n0)]);
                bh[j][1] = __float_as_uint(Bs[swz<BN>(kb+q+4, n0)]);
            }
            #pragma unroll
            for (int i = 0; i < MT; i++)
                #pragma unroll
                for (int j = 0; j < NT; j++)
                    mma_tf32(acc[i][j], ah[i], bh[j]);
        }
        __syncthreads();
    }

    #pragma unroll
    for (int i = 0; i < MT; i++) {
        #pragma unroll
        for (int half = 0; half < 2; half++) {
            int row = bm + wm0 + i*16 + g + half*8;
            #pragma unroll
            for (int j = 0; j < NT; j++) {
                int col = bn + wn0 + j*8 + 2*q;
                float v0 = acc[i][j][half*2 + 0];
                float v1 = acc[i][j][half*2 + 1];
                long base = (long)row*N + col;
                if (MODE == 1) {
                    v0 += RES[base]; v1 += RES[base + 1];
                } else if (MODE == 2) {
                    v0 += bias[col]; v1 += bias[col + 1];
                    v0 = (v0 > 20.f) ? v0 : log1pf(expf(v0));
                    v1 = (v1 > 20.f) ? v1 : log1pf(expf(v1));
                }
                *(float2*)(C + base) = make_float2(v0, v1);
            }
        }
    }
}

// ---------------------------------------------------------------------------
// Fused conv+silu+xproj (unchanged from passing R8 kernel).
// ---------------------------------------------------------------------------
__global__ void __launch_bounds__(128)
xproj_conv_kernel(const float* __restrict__ conv_w,
                  const float* __restrict__ conv_b,
                  const float* __restrict__ Wx)
{
    constexpr int BM = 64, BN = 64, BK = 32;
    constexpr int MT = 2, NT = 4;

    __shared__ float As[BK*BM];
    __shared__ float Bs[BK*BN];

    const int tid  = threadIdx.x;
    const int wid  = tid >> 5;
    const int lane = tid & 31;
    const int g    = lane >> 2;
    const int q    = lane & 3;
    const int wm0  = (wid & 1) * 32;
    const int wn0  = (wid >> 1) * 32;
    const int bm   = blockIdx.x * BM;

    float acc[MT][NT][4];
    #pragma unroll
    for (int i = 0; i < MT; i++)
        #pragma unroll
        for (int j = 0; j < NT; j++)
            #pragma unroll
            for (int v = 0; v < 4; v++) acc[i][j][v] = 0.f;

    for (int k0 = 0; k0 < DINNER; k0 += BK) {
        #pragma unroll
        for (int i = 0; i < 4; i++) {
            int idx = tid + i*128;
            int r = idx >> 3, c4 = idx & 7;
            int m = bm + r;
            int l = m & (LSEQ - 1);
            int k = k0 + c4*4;

            float tv[4][4];
            #pragma unroll
            for (int j = 0; j < 4; j++) {
                float4 t = make_float4(0.f, 0.f, 0.f, 0.f);
                if (l - 3 + j >= 0)
                    t = *(const float4*)(g_xz + (long)(m - 3 + j)*(2*DINNER) + k);
                tv[j][0] = t.x; tv[j][1] = t.y; tv[j][2] = t.z; tv[j][3] = t.w;
            }
            float4 cb = *(const float4*)(conv_b + k);
            float cbv[4] = {cb.x, cb.y, cb.z, cb.w};
            float xo[4];
            #pragma unroll
            for (int cc = 0; cc < 4; cc++) {
                float4 w = *(const float4*)(conv_w + (k + cc)*DCONV);
                float a = cbv[cc] + w.x*tv[0][cc] + w.y*tv[1][cc]
                                  + w.z*tv[2][cc] + w.w*tv[3][cc];
                float sig = 1.f / (1.f + __expf(-a));
                xo[cc] = a * sig;
                As[swz<BM>(c4*4 + cc, r)] = f2tf32(xo[cc]);
            }
            *(float4*)(g_xc + (long)m*DINNER + k) =
                make_float4(xo[0], xo[1], xo[2], xo[3]);
        }
        #pragma unroll
        for (int i = 0; i < 4; i++) {
            int idx = tid + i*128;
            int kr = idx >> 4, nc4 = idx & 15;
            float4 v = *(const float4*)(Wx + (long)(k0 + kr)*DBLC + nc4*4);
            float4 t;
            t.x = f2tf32(v.x); t.y = f2tf32(v.y);
            t.z = f2tf32(v.z); t.w = f2tf32(v.w);
            *(float4*)(Bs + swz<BN>(kr, nc4*4)) = t;
        }
        __syncthreads();

        #pragma unroll
        for (int kk = 0; kk < 4; kk++) {
            const int kb = kk*8;
            uint32_t ah[MT][4], bh[NT][2];
            #pragma unroll
            for (int i = 0; i < MT; i++) {
                int m0 = wm0 + i*16 + g;
                ah[i][0] = __float_as_uint(As[swz<BM>(kb+q,   m0    )]);
                ah[i][1] = __float_as_uint(As[swz<BM>(kb+q,   m0 + 8)]);
                ah[i][2] = __float_as_uint(As[swz<BM>(kb+q+4, m0    )]);
                ah[i][3] = __float_as_uint(As[swz<BM>(kb+q+4, m0 + 8)]);
            }
            #pragma unroll
            for (int j = 0; j < NT; j++) {
                int n0 = wn0 + j*8 + g;
                bh[j][0] = __float_as_uint(Bs[swz<BN>(kb+q,   n0)]);
                bh[j][1] = __float_as_uint(Bs[swz<BN>(kb+q+4, n0)]);
            }
            #pragma unroll
            for (int i = 0; i < MT; i++)
                #pragma unroll
                for (int j = 0; j < NT; j++)
                    mma_tf32(acc[i][j], ah[i], bh[j]);
        }
        __syncthreads();
    }

    #pragma unroll
    for (int i = 0; i < MT; i++) {
        #pragma unroll
        for (int half = 0; half < 2; half++) {
            int row = bm + wm0 + i*16 + g + half*8;
            #pragma unroll
            for (int j = 0; j < NT; j++) {
                int col = wn0 + j*8 + 2*q;
                *(float2*)(g_dbl + (long)row*DBLC + col) =
                    make_float2(acc[i][j][half*2 + 0], acc[i][j][half*2 + 1]);
            }
        }
    }
}

// ---------------------------------------------------------------------------
// Chunked parallel scan.
// Thread map (pass 1/3): gid -> s=gid&15, d=(gid>>4)&1023, ch=(gid>>14)&7, b=gid>>17
// Pass 1: per-chunk local scan from h=0. Stores partial y=C.h_local, h_end, P_end.
// ---------------------------------------------------------------------------
__global__ void __launch_bounds__(128) scan_part1(const float* __restrict__ A_log)
{
    int gid = blockIdx.x * 128 + threadIdx.x;
    int s  = gid & 15;
    int d  = (gid >> 4) & 1023;
    int ch = (gid >> 14) & 7;
    int b  = gid >> 17;

    const float A = -expf(A_log[d*DSTATE + s]);
    float h = 0.f, P = 1.f;

    int row = b*LSEQ + ch*CL;
    for (int t0 = 0; t0 < CL; t0 += 4, row += 4) {
        float dtv[4], xv[4], Bv[4], Cv[4];
        #pragma unroll
        for (int u = 0; u < 4; u++) {
            int r = row + u;
            dtv[u] = g_dt [(long)r*DINNER + d];
            xv [u] = g_xc [(long)r*DINNER + d];
            Bv [u] = g_dbl[(long)r*DBLC + DTRANK + s];
            Cv [u] = g_dbl[(long)r*DBLC + DTRANK + DSTATE + s];
        }
        float p[4];
        #pragma unroll
        for (int u = 0; u < 4; u++) {
            float dA = __expf(dtv[u] * A);
            h = h * dA + (dtv[u] * xv[u]) * Bv[u];
            P *= dA;
            p[u] = h * Cv[u];
        }
        #pragma unroll
        for (int off = 8; off; off >>= 1) {
            #pragma unroll
            for (int u = 0; u < 4; u++)
                p[u] += __shfl_xor_sync(0xffffffffu, p[u], off);
        }
        if (s == 0) {
            #pragma unroll
            for (int u = 0; u < 4; u++)
                g_y[(long)(row + u)*DINNER + d] = p[u];
        }
    }
    long idx = ((long)((b*NCH + ch)*DINNER + d))*DSTATE + s;
    g_hend[idx] = h;
    g_pend[idx] = P;
}

// Pass 2: chain chunk boundary states. gid -> s, d, b. 8-step sequential loop.
__global__ void __launch_bounds__(128) scan_combine()
{
    int gid = blockIdx.x * 128 + threadIdx.x;
    int s = gid & 15;
    int d = (gid >> 4) & 1023;
    int b = gid >> 14;

    float h = 0.f;
    #pragma unroll
    for (int c = 0; c < NCH; c++) {
        long idx = ((long)((b*NCH + c)*DINNER + d))*DSTATE + s;
        g_hin[idx] = h;
        h = g_pend[idx] * h + g_hend[idx];
    }
}

// Pass 3: add correction C.(Q_t o h_in), apply D-skip and silu(z) gating.
__global__ void __launch_bounds__(128) scan_part3(const float* __restrict__ A_log,
                                                  const float* __restrict__ Dvec)
{
    int gid = blockIdx.x * 128 + threadIdx.x;
    int s  = gid & 15;
    int d  = (gid >> 4) & 1023;
    int ch = (gid >> 14) & 7;
    int b  = gid >> 17;

    const float A  = -expf(A_log[d*DSTATE + s]);
    const float Dv = Dvec[d];
    const float hin = g_hin[((long)((b*NCH + ch)*DINNER + d))*DSTATE + s];
    float P = 1.f;

    int row = b*LSEQ + ch*CL;
    for (int t0 = 0; t0 < CL; t0 += 4, row += 4) {
        float dtv[4], Cv[4];
        #pragma unroll
        for (int u = 0; u < 4; u++) {
            int r = row + u;
            dtv[u] = g_dt [(long)r*DINNER + d];
            Cv [u] = g_dbl[(long)r*DBLC + DTRANK + DSTATE + s];
        }
        float p[4];
        #pragma unroll
        for (int u = 0; u < 4; u++) {
            P *= __expf(dtv[u] * A);
            p[u] = (P * hin) * Cv[u];
        }
        #pragma unroll
        for (int off = 8; off; off >>= 1) {
            #pragma unroll
            for (int u = 0; u < 4; u++)
                p[u] += __shfl_xor_sync(0xffffffffu, p[u], off);
        }
        if (s == 0) {
            #pragma unroll
            for (int u = 0; u < 4; u++) {
                int r = row + u;
                float y  = g_y[(long)r*DINNER + d] + p[u];
                float xv = g_xc[(long)r*DINNER + d];
                float zv = g_xz[(long)r*(2*DINNER) + DINNER + d];
                float sig = 1.f / (1.f + __expf(-zv));
                g_y[(long)r*DINNER + d] = (y + xv*Dv) * (zv * sig);
            }
        }
    }
}

// ---------------------------------------------------------------------------
// LayerNorm over rows of 512 (in-place)
// ---------------------------------------------------------------------------
__global__ void ln_kernel(float* __restrict__ out,
                          const float* __restrict__ gamma,
                          const float* __restrict__ beta)
{
    int row = blockIdx.x;
    int t   = threadIdx.x;
    float v0 = out[(long)row*DMODEL + t];
    float v1 = out[(long)row*DMODEL + 256 + t];

    float s = v0 + v1;
    float qq = v0*v0 + v1*v1;
    #pragma unroll
    for (int o = 16; o; o >>= 1) {
        s  += __shfl_xor_sync(0xffffffffu, s, o);
        qq += __shfl_xor_sync(0xffffffffu, qq, o);
    }
    __shared__ float s1[8], s2[8];
    int wid = t >> 5, lane = t & 31;
    if (lane == 0) { s1[wid] = s; s2[wid] = qq; }
    __syncthreads();
    if (t == 0) {
        float ts = 0.f, tq = 0.f;
        #pragma unroll
        for (int i = 0; i < 8; i++) { ts += s1[i]; tq += s2[i]; }
        float mu = ts / DMODEL;
        s1[0] = mu;
        s2[0] = tq / DMODEL - mu*mu;
    }
    __syncthreads();
    float mu  = s1[0];
    float inv = rsqrtf(s2[0] + 1e-5f);
    out[(long)row*DMODEL + t]       = (v0 - mu) * inv * gamma[t]       + beta[t];
    out[(long)row*DMODEL + 256 + t] = (v1 - mu) * inv * gamma[256 + t] + beta[256 + t];
}

// ---------------------------------------------------------------------------
extern "C" void kernel_launch(void* const* d_in, const int* in_sizes, int n_in,
                              void* d_out, int out_size)
{
    const float* x      = (const float*)d_in[0];
    const float* W_in   = (const float*)d_in[1];
    const float* conv_w = (const float*)d_in[2];
    const float* conv_b = (const float*)d_in[3];
    const float* W_xprj = (const float*)d_in[4];
    const float* W_dt   = (const float*)d_in[5];
    const float* b_dt   = (const float*)d_in[6];
    const float* A_log  = (const float*)d_in[7];
    const float* Dvec   = (const float*)d_in[8];
    const float* W_out  = (const float*)d_in[9];
    const float* gamma  = (const float*)d_in[10];
    const float* beta   = (const float*)d_in[11];
    float* out = (float*)d_out;

    float *xz, *dbl, *dt, *y;
    cudaGetSymbolAddress((void**)&xz,  g_xz);
    cudaGetSymbolAddress((void**)&dbl, g_dbl);
    cudaGetSymbolAddress((void**)&dt,  g_dt);
    cudaGetSymbolAddress((void**)&y,   g_y);

    const int SM128 = (32*128 + 32*128)*4;  // 32768

    // 0) xz = x @ W_in   (4096 x 2048, K=512)
    mma_gemm<128,128,4,2,0><<<dim3(2*DINNER/128, NROWS/128), 256, SM128>>>(
        x, DMODEL, W_in, 2*DINNER, nullptr, nullptr, xz, 2*DINNER, DMODEL);

    // 1) fused conv+silu+xproj
    xproj_conv_kernel<<<NROWS/64, 128>>>(conv_w, conv_b, W_xprj);

    // 2) dt = softplus(dtr @ W_dt + b_dt)
    mma_gemm<128,128,4,2,2><<<dim3(DINNER/128, NROWS/128), 256, SM128>>>(
        dbl, DBLC, W_dt, DINNER, nullptr, b_dt, dt, DINNER, DTRANK);

    // 3) chunked scan, pass 1  (launch index 3 -> ncu capture target)
    scan_part1<<<(BSZ*NCH*DINNER*DSTATE)/128, 128>>>(A_log);

    // 4) chunk boundary combine
    scan_combine<<<(BSZ*DINNER*DSTATE)/128, 128>>>();

    // 5) correction + gating
    scan_part3<<<(BSZ*NCH*DINNER*DSTATE)/128, 128>>>(A_log, Dvec);

    // 6) h2 = y @ W_out + x
    mma_gemm<128,128,4,2,1><<<dim3(DMODEL/128, NROWS/128), 256, SM128>>>(
        y, DINNER, W_out, DMODEL, x, nullptr, out, DMODEL, DINNER);

    // 7) LayerNorm
    ln_kernel<<<NROWS, 256>>>(out, gamma, beta);
}